// round 6
// baseline (speedup 1.0000x reference)
#include <cuda_runtime.h>
#include <cuda_bf16.h>
#include <math.h>

// Problem constants
#define NN      8000
#define NFEAT   512
#define NHID    128
#define NCLS    64
#define CAP     96
#define EPS     1e-12f

#define AST 20            // As smem stride (16 + 4 pad)
#define BST 136           // Bs smem stride (128 + 8 pad)

// ---------------- scratch (device globals; no allocation allowed) ------------
__device__ float g_h     [NN * NHID];
__device__ float g_li0   [NN * NHID];
__device__ float g_yhat  [NN * NCLS];
__device__ int   g_cols  [NN * CAP];
__device__ float g_w     [NN * CAP];
__device__ int   g_deg   [NN];
__device__ int   g_cnt   [NN];

// ---------------- helpers ----------------------------------------------------
__device__ __forceinline__ unsigned f2tf(float f) {
    unsigned u;
    asm("cvt.rna.tf32.f32 %0, %1;" : "=r"(u) : "f"(f));
    return u;
}

#define MMA_TF32(cc, a, b0_, b1_)                                              \
    asm volatile(                                                              \
        "mma.sync.aligned.m16n8k8.row.col.f32.tf32.tf32.f32 "                  \
        "{%0,%1,%2,%3}, {%4,%5,%6,%7}, {%8,%9}, {%0,%1,%2,%3};"                \
        : "+f"(cc[0]), "+f"(cc[1]), "+f"(cc[2]), "+f"(cc[3])                   \
        : "r"(a[0]), "r"(a[1]), "r"(a[2]), "r"(a[3]), "r"(b0_), "r"(b1_))

// =============================================================================
// KERNEL 1: GEMM1 (tensor tf32-split): h = relu(x @ W0 + b0)
// =============================================================================
__global__ __launch_bounds__(128) void gemm1_tc(const float* __restrict__ x,
                                                const float* __restrict__ W0,
                                                const float* __restrict__ b0) {
    __shared__ unsigned Ah[64 * AST], Al[64 * AST];
    __shared__ unsigned Bh[16 * BST], Bl[16 * BST];

    const int tid  = threadIdx.x;
    const int warp = tid >> 5;
    const int lane = tid & 31;
    const int m0   = blockIdx.x * 64;
    const int wm   = (warp & 1) * 32;
    const int wn   = (warp >> 1) * 64;

    float c[2][8][4];
#pragma unroll
    for (int mt = 0; mt < 2; mt++)
#pragma unroll
        for (int nt = 0; nt < 8; nt++)
#pragma unroll
            for (int r = 0; r < 4; r++) c[mt][nt][r] = 0.0f;

    const int ra = tid >> 1, ca = (tid & 1) * 8;
    const int rb = tid >> 3, cb = (tid & 7) * 16;
    float4 xa[2], wb[4];

    {
        const float* xp = x + (size_t)(m0 + ra) * NFEAT + ca;
        xa[0] = *(const float4*)(xp);
        xa[1] = *(const float4*)(xp + 4);
        const float* wp = W0 + (size_t)rb * NHID + cb;
#pragma unroll
        for (int i = 0; i < 4; i++) wb[i] = *(const float4*)(wp + i * 4);
    }

    for (int it = 0; it < 32; it++) {
        {
            const float* av = (const float*)xa;
#pragma unroll
            for (int j = 0; j < 8; j++) {
                float v  = av[j];
                unsigned hb = f2tf(v);
                Ah[ra * AST + ca + j] = hb;
                Al[ra * AST + ca + j] = f2tf(v - __uint_as_float(hb));
            }
            const float* bv = (const float*)wb;
#pragma unroll
            for (int j = 0; j < 16; j++) {
                float v  = bv[j];
                unsigned hb = f2tf(v);
                Bh[rb * BST + cb + j] = hb;
                Bl[rb * BST + cb + j] = f2tf(v - __uint_as_float(hb));
            }
        }
        __syncthreads();

        if (it < 31) {
            int k0 = (it + 1) * 16;
            const float* xp = x + (size_t)(m0 + ra) * NFEAT + k0 + ca;
            xa[0] = *(const float4*)(xp);
            xa[1] = *(const float4*)(xp + 4);
            const float* wp = W0 + (size_t)(k0 + rb) * NHID + cb;
#pragma unroll
            for (int i = 0; i < 4; i++) wb[i] = *(const float4*)(wp + i * 4);
        }

#pragma unroll
        for (int ks = 0; ks < 16; ks += 8) {
            unsigned ah[2][4], al[2][4];
            const int arow = wm + (lane >> 2);
            const int ac   = ks + (lane & 3);
#pragma unroll
            for (int mt = 0; mt < 2; mt++) {
                int r = arow + mt * 16;
                ah[mt][0] = Ah[r * AST + ac];
                ah[mt][1] = Ah[(r + 8) * AST + ac];
                ah[mt][2] = Ah[r * AST + ac + 4];
                ah[mt][3] = Ah[(r + 8) * AST + ac + 4];
                al[mt][0] = Al[r * AST + ac];
                al[mt][1] = Al[(r + 8) * AST + ac];
                al[mt][2] = Al[r * AST + ac + 4];
                al[mt][3] = Al[(r + 8) * AST + ac + 4];
            }
#pragma unroll
            for (int nt = 0; nt < 8; nt++) {
                const int bn = wn + nt * 8 + (lane >> 2);
                const int bk = ks + (lane & 3);
                unsigned bh0 = Bh[bk * BST + bn];
                unsigned bh1 = Bh[(bk + 4) * BST + bn];
                unsigned bl0 = Bl[bk * BST + bn];
                unsigned bl1 = Bl[(bk + 4) * BST + bn];
#pragma unroll
                for (int mt = 0; mt < 2; mt++) {
                    MMA_TF32(c[mt][nt], ah[mt], bh0, bh1);
                    MMA_TF32(c[mt][nt], ah[mt], bl0, bl1);
                    MMA_TF32(c[mt][nt], al[mt], bh0, bh1);
                }
            }
        }
        __syncthreads();
    }

#pragma unroll
    for (int nt = 0; nt < 8; nt++) {
        int col = wn + nt * 8 + 2 * (lane & 3);
        float bias0 = b0[col], bias1 = b0[col + 1];
#pragma unroll
        for (int mt = 0; mt < 2; mt++) {
            int r = m0 + wm + mt * 16 + (lane >> 2);
            g_h[(size_t)r * NHID + col]           = fmaxf(c[mt][nt][0] + bias0, 0.0f);
            g_h[(size_t)r * NHID + col + 1]       = fmaxf(c[mt][nt][1] + bias1, 0.0f);
            g_h[(size_t)(r + 8) * NHID + col]     = fmaxf(c[mt][nt][2] + bias0, 0.0f);
            g_h[(size_t)(r + 8) * NHID + col + 1] = fmaxf(c[mt][nt][3] + bias1, 0.0f);
        }
    }
}

// =============================================================================
// KERNEL cnt: train-index multiplicity histogram (tiny)
// =============================================================================
__global__ void cnt_kernel(const int* __restrict__ idx_tr) {
    int t = threadIdx.x;
    for (int i = t; i < NN; i += 256) g_cnt[i] = 0;
    __syncthreads();
    if (t < 250) {
        atomicAdd(&g_cnt[idx_tr[t]], 1);
        atomicAdd(&g_cnt[idx_tr[t + 250]], 1);
    }
}

// =============================================================================
// KERNEL 2: adjacency extraction (1 warp/row), 2x-unrolled loads (MLP=2)
// =============================================================================
__global__ __launch_bounds__(256) void extract_adj_kernel(const float* __restrict__ adj) {
    int row_id = blockIdx.x * 8 + (threadIdx.x >> 5);
    int lane = threadIdx.x & 31;
    const float* row = adj + (size_t)row_id * NN;
    int base = 0;
    // 8000 = 31*256 + 64
    for (int c0 = 0; c0 < 7936; c0 += 256) {
        float4 va = *(const float4*)(row + c0 + lane * 4);
        float4 vb = *(const float4*)(row + c0 + 128 + lane * 4);
        unsigned ma = (va.x != 0.0f) | ((va.y != 0.0f) << 1) |
                      ((va.z != 0.0f) << 2) | ((va.w != 0.0f) << 3);
        unsigned mb = (vb.x != 0.0f) | ((vb.y != 0.0f) << 1) |
                      ((vb.z != 0.0f) << 2) | ((vb.w != 0.0f) << 3);
        unsigned acta = __ballot_sync(0xffffffffu, ma != 0);
        unsigned actb = __ballot_sync(0xffffffffu, mb != 0);
        if ((acta | actb) == 0) continue;
        int nza = __popc(ma), nzb = __popc(mb);
        unsigned act = acta;
        while (act) {
            int l   = __ffs(act) - 1;
            int c_l = __shfl_sync(0xffffffffu, nza, l);
            if (lane == l) {
                int p = base;
                int col = c0 + lane * 4;
                if (ma & 1) { if (p < CAP) g_cols[row_id * CAP + p] = col;     p++; }
                if (ma & 2) { if (p < CAP) g_cols[row_id * CAP + p] = col + 1; p++; }
                if (ma & 4) { if (p < CAP) g_cols[row_id * CAP + p] = col + 2; p++; }
                if (ma & 8) { if (p < CAP) g_cols[row_id * CAP + p] = col + 3; }
            }
            base += c_l;
            act &= act - 1;
        }
        act = actb;
        while (act) {
            int l   = __ffs(act) - 1;
            int c_l = __shfl_sync(0xffffffffu, nzb, l);
            if (lane == l) {
                int p = base;
                int col = c0 + 128 + lane * 4;
                if (mb & 1) { if (p < CAP) g_cols[row_id * CAP + p] = col;     p++; }
                if (mb & 2) { if (p < CAP) g_cols[row_id * CAP + p] = col + 1; p++; }
                if (mb & 4) { if (p < CAP) g_cols[row_id * CAP + p] = col + 2; p++; }
                if (mb & 8) { if (p < CAP) g_cols[row_id * CAP + p] = col + 3; }
            }
            base += c_l;
            act &= act - 1;
        }
    }
    // tail: 64 columns
    {
        float2 v = *(const float2*)(row + 7936 + lane * 2);
        unsigned m2 = (v.x != 0.0f) | ((v.y != 0.0f) << 1);
        unsigned act = __ballot_sync(0xffffffffu, m2 != 0);
        int nz = __popc(m2);
        while (act) {
            int l   = __ffs(act) - 1;
            int c_l = __shfl_sync(0xffffffffu, nz, l);
            if (lane == l) {
                int p = base;
                int col = 7936 + lane * 2;
                if (m2 & 1) { if (p < CAP) g_cols[row_id * CAP + p] = col;     p++; }
                if (m2 & 2) { if (p < CAP) g_cols[row_id * CAP + p] = col + 1; }
            }
            base += c_l;
            act &= act - 1;
        }
    }
    if (lane == 0) g_deg[row_id] = base < CAP ? base : CAP;
}

// =============================================================================
// KERNEL 3: Pseudo = h@W1 + b1 + 0.1*cnt*y_label; emit; yhat = softmax
// 16 rows/block, W1 staged in smem, width-16 shuffle softmax.
// =============================================================================
__global__ __launch_bounds__(256) void pseudo_fused(const float* __restrict__ W1,
                                                    const float* __restrict__ b1,
                                                    const float* __restrict__ y_label,
                                                    float* __restrict__ out_pseudo) {
    __shared__ float W1s[NHID * NCLS];     // 32 KB
    __shared__ float hs[16][NHID];         // 8 KB
    __shared__ float ps[16][68];           // padded

    const int t = threadIdx.x;
    const int row0 = blockIdx.x * 16;

    // stage W1 (8192 floats) and h rows (2048 floats)
    for (int i = t * 4; i < NHID * NCLS; i += 1024)
        *(float4*)&W1s[i] = *(const float4*)&W1[i];
    for (int i = t * 4; i < 16 * NHID; i += 1024)
        *(float4*)&hs[0][i] = *(const float4*)&g_h[(size_t)row0 * NHID + i];
    __syncthreads();

    const int c = t & 63, rg = t >> 6;
    float bias = b1[c];
#pragma unroll
    for (int ri = 0; ri < 4; ri++) {
        int r = rg + ri * 4;
        float acc = bias;
#pragma unroll 16
        for (int k = 0; k < NHID; k++) acc += hs[r][k] * W1s[k * NCLS + c];
        int grow = row0 + r;
        int cnt = g_cnt[grow];
        if (cnt) acc += 0.1f * (float)cnt * y_label[(size_t)grow * NCLS + c];
        out_pseudo[(size_t)grow * NCLS + c] = acc;
        ps[r][c] = acc;
    }
    __syncthreads();

    // softmax: 16 threads per row, 4 cols each, width-16 shuffles
    const int row = t >> 4, c0 = (t & 15) * 4;
    float4 vv = *(float4*)&ps[row][c0];
    float m = fmaxf(fmaxf(vv.x, vv.y), fmaxf(vv.z, vv.w));
#pragma unroll
    for (int o = 8; o; o >>= 1) m = fmaxf(m, __shfl_xor_sync(0xffffffffu, m, o, 16));
    float e0 = expf(vv.x - m), e1 = expf(vv.y - m);
    float e2 = expf(vv.z - m), e3 = expf(vv.w - m);
    float s = e0 + e1 + e2 + e3;
#pragma unroll
    for (int o = 8; o; o >>= 1) s += __shfl_xor_sync(0xffffffffu, s, o, 16);
    float inv = 1.0f / s;
    float4 yo = make_float4(e0 * inv, e1 * inv, e2 * inv, e3 * inv);
    *(float4*)&g_yhat[(size_t)(row0 + row) * NCLS + c0] = yo;
}

// =============================================================================
// KERNEL 4: edge weights + propagation layer 0 (warp-split SpMM)
// =============================================================================
__global__ __launch_bounds__(128) void ew_prop0() {
    int row = blockIdx.x;
    __shared__ float yi[NCLS];
    __shared__ int   cs[CAP];
    __shared__ float ws[CAP];
    __shared__ float sp[4][NHID];
    __shared__ float w4[4];
    __shared__ float ssum;
    int t = threadIdx.x;
    int wid = t >> 5, lane = t & 31;
    int deg = g_deg[row];
    if (t < NCLS) yi[t] = g_yhat[(size_t)row * NCLS + t];
    if (t < deg)  cs[t] = g_cols[row * CAP + t];
    __syncthreads();

    // edge weights: warp-strided dot products
    for (int n = wid; n < deg; n += 4) {
        const float* yj = g_yhat + (size_t)cs[n] * NCLS;
        float p = yi[lane] * yj[lane] + yi[lane + 32] * yj[lane + 32];
#pragma unroll
        for (int o = 16; o; o >>= 1) p += __shfl_down_sync(0xffffffffu, p, o);
        if (lane == 0) ws[n] = p;
    }
    __syncthreads();
    if (t == 0) {
        float s = 0.0f;
        for (int n = 0; n < deg; n++) s += ws[n];
        ssum = fmaxf(s, EPS);
    }
    __syncthreads();
    if (t < deg) {
        float wn = ws[t] / ssum;
        ws[t] = wn;
        g_w[row * CAP + t] = wn;
    }
    __syncthreads();

    // warp-split SpMM: warp w takes n = w, w+4, ...; float4 per lane
    float4 acc = make_float4(0.f, 0.f, 0.f, 0.f);
    for (int n = wid; n < deg; n += 4) {
        float wv = ws[n];
        float4 hv = *(const float4*)&g_h[(size_t)cs[n] * NHID + lane * 4];
        acc.x += wv * hv.x; acc.y += wv * hv.y;
        acc.z += wv * hv.z; acc.w += wv * hv.w;
    }
    *(float4*)&sp[wid][lane * 4] = acc;
    __syncthreads();

    float v = sp[0][t] + sp[1][t] + sp[2][t] + sp[3][t];
    v = 0.9f * v + 0.1f * g_h[(size_t)row * NHID + t];

    float q = v * v;
#pragma unroll
    for (int o = 16; o; o >>= 1) q += __shfl_xor_sync(0xffffffffu, q, o);
    if (lane == 0) w4[wid] = q;
    __syncthreads();
    float nrm = fmaxf(sqrtf(w4[0] + w4[1] + w4[2] + w4[3]), EPS);
    g_li0[(size_t)row * NHID + t] = v / nrm;
}

// =============================================================================
// KERNEL 5: propagation layer 1 + log_softmax(li1 @ W2 + b2) (warp-split SpMM)
// =============================================================================
__global__ __launch_bounds__(128) void prop1_final(const float* __restrict__ W2,
                                                   const float* __restrict__ b2,
                                                   float* __restrict__ out) {
    int row = blockIdx.x;
    __shared__ int   cs[CAP];
    __shared__ float ws[CAP];
    __shared__ float sp[4][NHID];
    __shared__ float li[NHID];
    __shared__ float pacc[NHID];
    __shared__ float w4[4];
    __shared__ float sm[4];
    int t = threadIdx.x;
    int wid = t >> 5, lane = t & 31;
    int deg = g_deg[row];
    if (t < deg) { cs[t] = g_cols[row * CAP + t]; ws[t] = g_w[row * CAP + t]; }
    __syncthreads();

    float4 acc4 = make_float4(0.f, 0.f, 0.f, 0.f);
    for (int n = wid; n < deg; n += 4) {
        float wv = ws[n];
        float4 hv = *(const float4*)&g_li0[(size_t)cs[n] * NHID + lane * 4];
        acc4.x += wv * hv.x; acc4.y += wv * hv.y;
        acc4.z += wv * hv.z; acc4.w += wv * hv.w;
    }
    *(float4*)&sp[wid][lane * 4] = acc4;
    __syncthreads();

    float v = sp[0][t] + sp[1][t] + sp[2][t] + sp[3][t];
    v = 0.9f * v + 0.1f * g_h[(size_t)row * NHID + t];

    float q = v * v;
#pragma unroll
    for (int o = 16; o; o >>= 1) q += __shfl_xor_sync(0xffffffffu, q, o);
    if (lane == 0) w4[wid] = q;
    __syncthreads();
    float nrm = fmaxf(sqrtf(w4[0] + w4[1] + w4[2] + w4[3]), EPS);
    li[t] = v / nrm;
    __syncthreads();

    // split-K gemm: out[c] = Σ_k li[k] * W2[k*64+c]
    int c = t & 63, ph = t >> 6;
    float a = 0.0f;
#pragma unroll 8
    for (int k = ph * 64; k < ph * 64 + 64; k++) a += li[k] * W2[k * NCLS + c];
    pacc[t] = a;
    __syncthreads();

    float acc = pacc[c] + pacc[64 + c] + b2[c];

    float m = acc;
#pragma unroll
    for (int o = 16; o; o >>= 1) m = fmaxf(m, __shfl_xor_sync(0xffffffffu, m, o));
    if (lane == 0) sm[wid] = m;
    __syncthreads();
    m = fmaxf(sm[0], sm[1]);
    __syncthreads();
    float sh = acc - m;
    float e = expf(sh);
    float ss = e;
#pragma unroll
    for (int o = 16; o; o >>= 1) ss += __shfl_xor_sync(0xffffffffu, ss, o);
    if (lane == 0) sm[wid] = ss;
    __syncthreads();
    ss = sm[0] + sm[1];
    if (t < 64) out[(size_t)row * NCLS + c] = sh - logf(ss);
}

// ---------------- launch: 2-stream fork/join inside the captured graph --------
extern "C" void kernel_launch(void* const* d_in, const int* in_sizes, int n_in,
                              void* d_out, int out_size) {
    const float* x      = (const float*)d_in[0];
    const float* adj    = (const float*)d_in[1];
    const float* y_lab  = (const float*)d_in[2];
    const int*   idx_tr = (const int*)  d_in[3];
    const float* W0     = (const float*)d_in[4];
    const float* b0     = (const float*)d_in[5];
    const float* W1     = (const float*)d_in[6];
    const float* b1     = (const float*)d_in[7];
    const float* W2     = (const float*)d_in[8];
    const float* b2     = (const float*)d_in[9];
    float* out = (float*)d_out;

    static cudaStream_t s2 = nullptr;
    static cudaEvent_t evFork = nullptr, evCnt = nullptr, evExt = nullptr;
    if (s2 == nullptr) {
        cudaStreamCreateWithFlags(&s2, cudaStreamNonBlocking);
        cudaEventCreateWithFlags(&evFork, cudaEventDisableTiming);
        cudaEventCreateWithFlags(&evCnt,  cudaEventDisableTiming);
        cudaEventCreateWithFlags(&evExt,  cudaEventDisableTiming);
    }

    cudaEventRecord(evFork, 0);
    cudaStreamWaitEvent(s2, evFork, 0);

    cnt_kernel<<<1, 256, 0, s2>>>(idx_tr);
    cudaEventRecord(evCnt, s2);
    extract_adj_kernel<<<1000, 256, 0, s2>>>(adj);
    cudaEventRecord(evExt, s2);

    gemm1_tc<<<NN / 64, 128>>>(x, W0, b0);                       // stream 0
    cudaStreamWaitEvent(0, evCnt, 0);
    pseudo_fused<<<NN / 16, 256>>>(W1, b1, y_lab, out + (size_t)NN * NCLS);
    cudaStreamWaitEvent(0, evExt, 0);
    ew_prop0<<<NN, 128>>>();
    prop1_final<<<NN, 128>>>(W2, b2, out);
}

// round 7
// speedup vs baseline: 2.0111x; 2.0111x over previous
#include <cuda_runtime.h>
#include <cuda_bf16.h>
#include <math.h>

// Problem constants
#define NN      8000
#define NFEAT   512
#define NHID    128
#define NCLS    64
#define CAP     96
#define EPS     1e-12f

#define AST 20            // As smem stride (16 + 4 pad)
#define BST 136           // Bs smem stride (128 + 8 pad)

// ---------------- scratch (device globals; no allocation allowed) ------------
__device__ float g_h     [NN * NHID];
__device__ float g_li0   [NN * NHID];
__device__ float g_yhat  [NN * NCLS];
__device__ int   g_cols  [NN * CAP];
__device__ float g_w     [NN * CAP];
__device__ int   g_deg   [NN];
__device__ int   g_cnt   [NN];

// ---------------- helpers ----------------------------------------------------
__device__ __forceinline__ unsigned f2tf(float f) {
    unsigned u;
    asm("cvt.rna.tf32.f32 %0, %1;" : "=r"(u) : "f"(f));
    return u;
}

#define MMA_TF32(cc, a, b0_, b1_)                                              \
    asm volatile(                                                              \
        "mma.sync.aligned.m16n8k8.row.col.f32.tf32.tf32.f32 "                  \
        "{%0,%1,%2,%3}, {%4,%5,%6,%7}, {%8,%9}, {%0,%1,%2,%3};"                \
        : "+f"(cc[0]), "+f"(cc[1]), "+f"(cc[2]), "+f"(cc[3])                   \
        : "r"(a[0]), "r"(a[1]), "r"(a[2]), "r"(a[3]), "r"(b0_), "r"(b1_))

// =============================================================================
// KERNEL 1: GEMM1 (tensor tf32-split): h = relu(x @ W0 + b0)   [R5 verbatim]
// =============================================================================
__global__ __launch_bounds__(128) void gemm1_tc(const float* __restrict__ x,
                                                const float* __restrict__ W0,
                                                const float* __restrict__ b0) {
    __shared__ unsigned Ah[64 * AST], Al[64 * AST];
    __shared__ unsigned Bh[16 * BST], Bl[16 * BST];

    const int tid  = threadIdx.x;
    const int warp = tid >> 5;
    const int lane = tid & 31;
    const int m0   = blockIdx.x * 64;
    const int wm   = (warp & 1) * 32;
    const int wn   = (warp >> 1) * 64;

    float c[2][8][4];
#pragma unroll
    for (int mt = 0; mt < 2; mt++)
#pragma unroll
        for (int nt = 0; nt < 8; nt++)
#pragma unroll
            for (int r = 0; r < 4; r++) c[mt][nt][r] = 0.0f;

    const int ra = tid >> 1, ca = (tid & 1) * 8;
    const int rb = tid >> 3, cb = (tid & 7) * 16;
    float4 xa[2], wb[4];

    {
        const float* xp = x + (size_t)(m0 + ra) * NFEAT + ca;
        xa[0] = *(const float4*)(xp);
        xa[1] = *(const float4*)(xp + 4);
        const float* wp = W0 + (size_t)rb * NHID + cb;
#pragma unroll
        for (int i = 0; i < 4; i++) wb[i] = *(const float4*)(wp + i * 4);
    }

    for (int it = 0; it < 32; it++) {
        {
            const float* av = (const float*)xa;
#pragma unroll
            for (int j = 0; j < 8; j++) {
                float v  = av[j];
                unsigned hb = f2tf(v);
                Ah[ra * AST + ca + j] = hb;
                Al[ra * AST + ca + j] = f2tf(v - __uint_as_float(hb));
            }
            const float* bv = (const float*)wb;
#pragma unroll
            for (int j = 0; j < 16; j++) {
                float v  = bv[j];
                unsigned hb = f2tf(v);
                Bh[rb * BST + cb + j] = hb;
                Bl[rb * BST + cb + j] = f2tf(v - __uint_as_float(hb));
            }
        }
        __syncthreads();

        if (it < 31) {
            int k0 = (it + 1) * 16;
            const float* xp = x + (size_t)(m0 + ra) * NFEAT + k0 + ca;
            xa[0] = *(const float4*)(xp);
            xa[1] = *(const float4*)(xp + 4);
            const float* wp = W0 + (size_t)(k0 + rb) * NHID + cb;
#pragma unroll
            for (int i = 0; i < 4; i++) wb[i] = *(const float4*)(wp + i * 4);
        }

#pragma unroll
        for (int ks = 0; ks < 16; ks += 8) {
            unsigned ah[2][4], al[2][4];
            const int arow = wm + (lane >> 2);
            const int ac   = ks + (lane & 3);
#pragma unroll
            for (int mt = 0; mt < 2; mt++) {
                int r = arow + mt * 16;
                ah[mt][0] = Ah[r * AST + ac];
                ah[mt][1] = Ah[(r + 8) * AST + ac];
                ah[mt][2] = Ah[r * AST + ac + 4];
                ah[mt][3] = Ah[(r + 8) * AST + ac + 4];
                al[mt][0] = Al[r * AST + ac];
                al[mt][1] = Al[(r + 8) * AST + ac];
                al[mt][2] = Al[r * AST + ac + 4];
                al[mt][3] = Al[(r + 8) * AST + ac + 4];
            }
#pragma unroll
            for (int nt = 0; nt < 8; nt++) {
                const int bn = wn + nt * 8 + (lane >> 2);
                const int bk = ks + (lane & 3);
                unsigned bh0 = Bh[bk * BST + bn];
                unsigned bh1 = Bh[(bk + 4) * BST + bn];
                unsigned bl0 = Bl[bk * BST + bn];
                unsigned bl1 = Bl[(bk + 4) * BST + bn];
#pragma unroll
                for (int mt = 0; mt < 2; mt++) {
                    MMA_TF32(c[mt][nt], ah[mt], bh0, bh1);
                    MMA_TF32(c[mt][nt], ah[mt], bl0, bl1);
                    MMA_TF32(c[mt][nt], al[mt], bh0, bh1);
                }
            }
        }
        __syncthreads();
    }

#pragma unroll
    for (int nt = 0; nt < 8; nt++) {
        int col = wn + nt * 8 + 2 * (lane & 3);
        float bias0 = b0[col], bias1 = b0[col + 1];
#pragma unroll
        for (int mt = 0; mt < 2; mt++) {
            int r = m0 + wm + mt * 16 + (lane >> 2);
            g_h[(size_t)r * NHID + col]           = fmaxf(c[mt][nt][0] + bias0, 0.0f);
            g_h[(size_t)r * NHID + col + 1]       = fmaxf(c[mt][nt][1] + bias1, 0.0f);
            g_h[(size_t)(r + 8) * NHID + col]     = fmaxf(c[mt][nt][2] + bias0, 0.0f);
            g_h[(size_t)(r + 8) * NHID + col + 1] = fmaxf(c[mt][nt][3] + bias1, 0.0f);
        }
    }
}

// =============================================================================
// KERNEL cnt: train-index multiplicity histogram (tiny)   [R5 verbatim]
// =============================================================================
__global__ void cnt_kernel(const int* __restrict__ idx_tr) {
    int t = threadIdx.x;
    for (int i = t; i < NN; i += 256) g_cnt[i] = 0;
    __syncthreads();
    if (t < 250) {
        atomicAdd(&g_cnt[idx_tr[t]], 1);
        atomicAdd(&g_cnt[idx_tr[t + 250]], 1);
    }
}

// =============================================================================
// KERNEL 2: adjacency extraction (1 warp/row)   [R5 verbatim]
// =============================================================================
__global__ __launch_bounds__(256) void extract_adj_kernel(const float* __restrict__ adj) {
    int row_id = blockIdx.x * 8 + (threadIdx.x >> 5);
    int lane = threadIdx.x & 31;
    const float* row = adj + (size_t)row_id * NN;
    int base = 0;
    for (int c0 = 0; c0 < 7936; c0 += 128) {
        float4 v = *(const float4*)(row + c0 + lane * 4);
        unsigned m4 = (v.x != 0.0f) | ((v.y != 0.0f) << 1) |
                      ((v.z != 0.0f) << 2) | ((v.w != 0.0f) << 3);
        unsigned act = __ballot_sync(0xffffffffu, m4 != 0);
        if (act == 0) continue;
        int nz = __popc(m4);
        while (act) {
            int l   = __ffs(act) - 1;
            int c_l = __shfl_sync(0xffffffffu, nz, l);
            if (lane == l) {
                int p = base;
                int col = c0 + lane * 4;
                if (m4 & 1) { if (p < CAP) g_cols[row_id * CAP + p] = col;     p++; }
                if (m4 & 2) { if (p < CAP) g_cols[row_id * CAP + p] = col + 1; p++; }
                if (m4 & 4) { if (p < CAP) g_cols[row_id * CAP + p] = col + 2; p++; }
                if (m4 & 8) { if (p < CAP) g_cols[row_id * CAP + p] = col + 3; }
            }
            base += c_l;
            act &= act - 1;
        }
    }
    {
        float2 v = *(const float2*)(row + 7936 + lane * 2);
        unsigned m2 = (v.x != 0.0f) | ((v.y != 0.0f) << 1);
        unsigned act = __ballot_sync(0xffffffffu, m2 != 0);
        int nz = __popc(m2);
        while (act) {
            int l   = __ffs(act) - 1;
            int c_l = __shfl_sync(0xffffffffu, nz, l);
            if (lane == l) {
                int p = base;
                int col = 7936 + lane * 2;
                if (m2 & 1) { if (p < CAP) g_cols[row_id * CAP + p] = col;     p++; }
                if (m2 & 2) { if (p < CAP) g_cols[row_id * CAP + p] = col + 1; }
            }
            base += c_l;
            act &= act - 1;
        }
    }
    if (lane == 0) g_deg[row_id] = base < CAP ? base : CAP;
}

// =============================================================================
// KERNEL 3: Pseudo fused   [R5 verbatim — 4 rows/block version]
// =============================================================================
__global__ void pseudo_fused(const float* __restrict__ W1,
                             const float* __restrict__ b1,
                             const float* __restrict__ y_label,
                             float* __restrict__ out_pseudo) {
    int ry = threadIdx.y, c = threadIdx.x;
    int row = blockIdx.x * 4 + ry;
    __shared__ float hr[4][128];
    hr[ry][c]      = g_h[(size_t)row * NHID + c];
    hr[ry][c + 64] = g_h[(size_t)row * NHID + c + 64];
    __syncthreads();
    float acc = b1[c];
#pragma unroll 8
    for (int k = 0; k < NHID; k++) acc += hr[ry][k] * W1[k * NCLS + c];

    int cnt = g_cnt[row];
    if (cnt) acc += 0.1f * (float)cnt * y_label[(size_t)row * NCLS + c];

    out_pseudo[(size_t)row * NCLS + c] = acc;

    __shared__ float sm[4][2];
    int wu = c >> 5, lane = c & 31;
    float m = acc;
#pragma unroll
    for (int o = 16; o; o >>= 1) m = fmaxf(m, __shfl_xor_sync(0xffffffffu, m, o));
    if (lane == 0) sm[ry][wu] = m;
    __syncthreads();
    m = fmaxf(sm[ry][0], sm[ry][1]);
    __syncthreads();
    float e = expf(acc - m);
    float s = e;
#pragma unroll
    for (int o = 16; o; o >>= 1) s += __shfl_xor_sync(0xffffffffu, s, o);
    if (lane == 0) sm[ry][wu] = s;
    __syncthreads();
    s = sm[ry][0] + sm[ry][1];
    g_yhat[(size_t)row * NCLS + c] = e / s;
}

// =============================================================================
// KERNEL 4: edge weights + propagation layer 0
// [R5 structure; ONLY change: 4x-unrolled independent-load SpMM + shuffle norm]
// =============================================================================
__global__ __launch_bounds__(128) void ew_prop0() {
    int row = blockIdx.x;
    __shared__ float yi[NCLS];
    __shared__ int   cs[CAP];
    __shared__ float ws[CAP];
    __shared__ float w4[4];
    __shared__ float ssum;
    int t = threadIdx.x;
    int wid = t >> 5, lane = t & 31;
    int deg = g_deg[row];
    if (t < NCLS) yi[t] = g_yhat[(size_t)row * NCLS + t];
    if (t < deg)  cs[t] = g_cols[row * CAP + t];
    __syncthreads();

    for (int n = wid; n < deg; n += 4) {
        const float* yj = g_yhat + (size_t)cs[n] * NCLS;
        float p = yi[lane] * yj[lane] + yi[lane + 32] * yj[lane + 32];
#pragma unroll
        for (int o = 16; o; o >>= 1) p += __shfl_down_sync(0xffffffffu, p, o);
        if (lane == 0) ws[n] = p;
    }
    __syncthreads();
    if (t == 0) {
        float s = 0.0f;
        for (int n = 0; n < deg; n++) s += ws[n];
        ssum = fmaxf(s, EPS);
    }
    __syncthreads();
    if (t < deg) {
        float wn = ws[t] / ssum;
        ws[t] = wn;
        g_w[row * CAP + t] = wn;
    }
    __syncthreads();

    // SpMM, 4x unrolled with independent loads (MLP=4)
    float s = 0.0f;
    int n = 0;
    for (; n + 4 <= deg; n += 4) {
        float a0 = g_h[(size_t)cs[n]     * NHID + t];
        float a1 = g_h[(size_t)cs[n + 1] * NHID + t];
        float a2 = g_h[(size_t)cs[n + 2] * NHID + t];
        float a3 = g_h[(size_t)cs[n + 3] * NHID + t];
        s += ws[n] * a0 + ws[n + 1] * a1 + ws[n + 2] * a2 + ws[n + 3] * a3;
    }
    for (; n < deg; n++) s += ws[n] * g_h[(size_t)cs[n] * NHID + t];

    float v = 0.9f * s + 0.1f * g_h[(size_t)row * NHID + t];

    // L2 norm via shuffles + 4-word combine
    float q = v * v;
#pragma unroll
    for (int o = 16; o; o >>= 1) q += __shfl_xor_sync(0xffffffffu, q, o);
    if (lane == 0) w4[wid] = q;
    __syncthreads();
    float nrm = fmaxf(sqrtf(w4[0] + w4[1] + w4[2] + w4[3]), EPS);
    g_li0[(size_t)row * NHID + t] = v / nrm;
}

// =============================================================================
// KERNEL 5: propagation layer 1 + log_softmax(li1 @ W2 + b2)
// [R5 structure; ONLY change: 4x-unrolled SpMM + shuffle norm]
// =============================================================================
__global__ __launch_bounds__(128) void prop1_final(const float* __restrict__ W2,
                                                   const float* __restrict__ b2,
                                                   float* __restrict__ out) {
    int row = blockIdx.x;
    __shared__ int   cs[CAP];
    __shared__ float ws[CAP];
    __shared__ float li[NHID];
    __shared__ float pacc[NHID];
    __shared__ float w4[4];
    __shared__ float sm[4];
    int t = threadIdx.x;
    int wid = t >> 5, lane = t & 31;
    int deg = g_deg[row];
    if (t < deg) { cs[t] = g_cols[row * CAP + t]; ws[t] = g_w[row * CAP + t]; }
    __syncthreads();

    float s = 0.0f;
    int n = 0;
    for (; n + 4 <= deg; n += 4) {
        float a0 = g_li0[(size_t)cs[n]     * NHID + t];
        float a1 = g_li0[(size_t)cs[n + 1] * NHID + t];
        float a2 = g_li0[(size_t)cs[n + 2] * NHID + t];
        float a3 = g_li0[(size_t)cs[n + 3] * NHID + t];
        s += ws[n] * a0 + ws[n + 1] * a1 + ws[n + 2] * a2 + ws[n + 3] * a3;
    }
    for (; n < deg; n++) s += ws[n] * g_li0[(size_t)cs[n] * NHID + t];

    float v = 0.9f * s + 0.1f * g_h[(size_t)row * NHID + t];

    float q = v * v;
#pragma unroll
    for (int o = 16; o; o >>= 1) q += __shfl_xor_sync(0xffffffffu, q, o);
    if (lane == 0) w4[wid] = q;
    __syncthreads();
    float nrm = fmaxf(sqrtf(w4[0] + w4[1] + w4[2] + w4[3]), EPS);
    li[t] = v / nrm;
    __syncthreads();

    int c = t & 63, ph = t >> 6;
    float a = 0.0f;
#pragma unroll 8
    for (int k = ph * 64; k < ph * 64 + 64; k++) a += li[k] * W2[k * NCLS + c];
    pacc[t] = a;
    __syncthreads();

    float acc = pacc[c] + pacc[64 + c] + b2[c];

    float m = acc;
#pragma unroll
    for (int o = 16; o; o >>= 1) m = fmaxf(m, __shfl_xor_sync(0xffffffffu, m, o));
    if (lane == 0) sm[wid] = m;
    __syncthreads();
    m = fmaxf(sm[0], sm[1]);
    __syncthreads();
    float sh = acc - m;
    float e = expf(sh);
    float ss = e;
#pragma unroll
    for (int o = 16; o; o >>= 1) ss += __shfl_xor_sync(0xffffffffu, ss, o);
    if (lane == 0) sm[wid] = ss;
    __syncthreads();
    ss = sm[0] + sm[1];
    if (t < 64) out[(size_t)row * NCLS + c] = sh - logf(ss);
}

// ---------------- launch: 2-stream fork/join inside the captured graph --------
extern "C" void kernel_launch(void* const* d_in, const int* in_sizes, int n_in,
                              void* d_out, int out_size) {
    const float* x      = (const float*)d_in[0];
    const float* adj    = (const float*)d_in[1];
    const float* y_lab  = (const float*)d_in[2];
    const int*   idx_tr = (const int*)  d_in[3];
    const float* W0     = (const float*)d_in[4];
    const float* b0     = (const float*)d_in[5];
    const float* W1     = (const float*)d_in[6];
    const float* b1     = (const float*)d_in[7];
    const float* W2     = (const float*)d_in[8];
    const float* b2     = (const float*)d_in[9];
    float* out = (float*)d_out;

    static cudaStream_t s2 = nullptr;
    static cudaEvent_t evFork = nullptr, evCnt = nullptr, evExt = nullptr;
    if (s2 == nullptr) {
        cudaStreamCreateWithFlags(&s2, cudaStreamNonBlocking);
        cudaEventCreateWithFlags(&evFork, cudaEventDisableTiming);
        cudaEventCreateWithFlags(&evCnt,  cudaEventDisableTiming);
        cudaEventCreateWithFlags(&evExt,  cudaEventDisableTiming);
    }

    cudaEventRecord(evFork, 0);
    cudaStreamWaitEvent(s2, evFork, 0);

    cnt_kernel<<<1, 256, 0, s2>>>(idx_tr);
    cudaEventRecord(evCnt, s2);
    extract_adj_kernel<<<1000, 256, 0, s2>>>(adj);
    cudaEventRecord(evExt, s2);

    gemm1_tc<<<NN / 64, 128>>>(x, W0, b0);                       // stream 0
    cudaStreamWaitEvent(0, evCnt, 0);
    pseudo_fused<<<NN / 4, dim3(64, 4)>>>(W1, b1, y_lab, out + (size_t)NN * NCLS);
    cudaStreamWaitEvent(0, evExt, 0);
    ew_prop0<<<NN, 128>>>();
    prop1_final<<<NN, 128>>>(W2, b2, out);
}